// round 16
// baseline (speedup 1.0000x reference)
#include <cuda_runtime.h>

#define Bz 8
#define Cc 512
#define Nn 2048
#define Dd 128
#define INV_SCALE 0.08838834764831845f   // 1/sqrt(128)

typedef unsigned long long ull;
typedef unsigned int u32;

// ------------------------- scratch (__device__ globals) --------------------
__device__ float g_qk [(size_t)Bz * Dd * Nn];   // [b][d][n]  8 MB
__device__ float g_v  [(size_t)Bz * Dd * Nn];   // [b][d][n]  8 MB
__device__ float g_vT [(size_t)Bz * Nn * Dd];   // [b][n][d] = v*linv  8 MB
__device__ float g_wT [2 * Cc * Dd];            // W transposed [which][c][d]
__device__ float g_P  [(size_t)Bz * Nn * Nn];   // exp(e) unnormalized, 128 MB
__device__ float g_lsum[Bz * Nn];
__device__ float g_linv[Bz * Nn];

// ------------------------- helpers -----------------------------------------
__device__ __forceinline__ u32 smem_u32(const void* p) {
    u32 a;
    asm("{ .reg .u64 t; cvta.to.shared.u64 t, %1; cvt.u32.u64 %0, t; }"
        : "=r"(a) : "l"(p));
    return a;
}
__device__ __forceinline__ void cp16(u32 dst, const float* src) {
    asm volatile("cp.async.ca.shared.global [%0], [%1], 16;"
                 :: "r"(dst), "l"(src));
}
#define CP_COMMIT() asm volatile("cp.async.commit_group;" ::: "memory")
#define CP_WAIT(n)  asm volatile("cp.async.wait_group %0;" :: "n"(n) : "memory")

__device__ __forceinline__ void fma2(ull& d, ull a, ull b) {
    asm("fma.rn.f32x2 %0, %1, %2, %0;" : "+l"(d) : "l"(a), "l"(b));
}
__device__ __forceinline__ ull pk2(float x) {
    ull r; asm("mov.b64 %0, {%1, %1};" : "=l"(r) : "f"(x)); return r;
}
__device__ __forceinline__ float2 upk(ull v) {
    float2 f; asm("mov.b64 {%0, %1}, %2;" : "=f"(f.x), "=f"(f.y) : "l"(v)); return f;
}

// 8x16 thread tile, 128 threads -> 128x128 CTA tile.
// trow = (tid>>3)*8 (A/row dim), tcol = (tid&7)*16 (B/col dim).
// Per warp-k: A loads broadcast (4 distinct ty), B loads 128B dedup'd -> ~6 wf
// vs 128 fma-pipe cycles: LDS no longer co-saturated with FMA.
#define MMA8x16(Ap, Bp)                                                        \
    {                                                                          \
        float4 a0 = *(const float4*)&(Ap)[trow];                               \
        float4 a1 = *(const float4*)&(Ap)[trow + 4];                           \
        ulonglong2 b01 = *(const ulonglong2*)&(Bp)[tcol];                      \
        ulonglong2 b23 = *(const ulonglong2*)&(Bp)[tcol + 4];                  \
        ulonglong2 b45 = *(const ulonglong2*)&(Bp)[tcol + 8];                  \
        ulonglong2 b67 = *(const ulonglong2*)&(Bp)[tcol + 12];                 \
        float a[8] = {a0.x, a0.y, a0.z, a0.w, a1.x, a1.y, a1.z, a1.w};         \
        _Pragma("unroll")                                                      \
        for (int r = 0; r < 8; ++r) {                                          \
            ull ad = pk2(a[r]);                                                \
            fma2(acc[r][0], ad, b01.x); fma2(acc[r][1], ad, b01.y);            \
            fma2(acc[r][2], ad, b23.x); fma2(acc[r][3], ad, b23.y);            \
            fma2(acc[r][4], ad, b45.x); fma2(acc[r][5], ad, b45.y);            \
            fma2(acc[r][6], ad, b67.x); fma2(acc[r][7], ad, b67.y);            \
        }                                                                      \
    }

// ---- 3-stage pipelined 128x128 GEMM engine (128 threads) -------------------
// smem: bufA = sm[0 .. 3*4096), bufB = sm[12288 .. +3*4096)  (96 KB)
// One __syncthreads per chunk: wait(1) -> sync -> issue(c+2) -> compute(c).
#define GISSUE(Abase, strideA, Bbase, strideB, c0, stg)                        \
    {                                                                          \
        u32 dA = sA + (stg) * 16384, dB = sB + (stg) * 16384;                  \
        _Pragma("unroll")                                                      \
        for (int q = 0; q < 8; ++q) {                                          \
            int slot = tid + q * 128;                                          \
            int row = slot >> 5, col4 = (slot & 31) * 4;                       \
            cp16(dA + slot * 16, (Abase) + (size_t)((c0) + row) * (strideA) + col4); \
            cp16(dB + slot * 16, (Bbase) + (size_t)((c0) + row) * (strideB) + col4); \
        }                                                                      \
        CP_COMMIT();                                                           \
    }

#define GEMM_LOOP(NC, Abase, strideA, Bbase, strideB)                          \
    GISSUE(Abase, strideA, Bbase, strideB, 0, 0);                              \
    GISSUE(Abase, strideA, Bbase, strideB, 32, 1);                             \
    for (int c = 0; c < (NC); ++c) {                                           \
        if (c + 1 < (NC)) { CP_WAIT(1); } else { CP_WAIT(0); }                 \
        __syncthreads();                                                       \
        if (c + 2 < (NC))                                                      \
            GISSUE(Abase, strideA, Bbase, strideB, (c + 2) * 32, (c + 2) % 3); \
        const float* A_ = bufA + (c % 3) * 4096;                               \
        const float* B_ = bufB + (c % 3) * 4096;                               \
        _Pragma("unroll")                                                      \
        for (int kk = 0; kk < 32; ++kk) MMA8x16(A_ + kk * 128, B_ + kk * 128); \
    }

#define GEMM_SMEM 98304

// ---------------------------------------------------------------------------
// tiny helpers
// ---------------------------------------------------------------------------
__global__ void zero_kernel() {
    int i = blockIdx.x * 1024 + threadIdx.x;
    if (i < Bz * Nn) g_lsum[i] = 0.0f;
}
__global__ void inv_kernel() {
    int i = blockIdx.x * 1024 + threadIdx.x;
    if (i < Bz * Nn) g_linv[i] = 1.0f / g_lsum[i];
}
__global__ void k_wT(const float* __restrict__ wqk, const float* __restrict__ wv) {
    __shared__ float T[32][33];
    const int ct = blockIdx.x, dt = blockIdx.y, which = blockIdx.z;
    const float* W = which ? wv : wqk;
    float* WT = g_wT + which * Cc * Dd;
    const int tx = threadIdx.x, ty = threadIdx.y;
    for (int yy = ty; yy < 32; yy += 8)
        T[yy][tx] = W[(dt * 32 + yy) * Cc + ct * 32 + tx];
    __syncthreads();
    for (int yy = ty; yy < 32; yy += 8)
        WT[(ct * 32 + yy) * Dd + dt * 32 + tx] = T[tx][yy];
}
__global__ void k_vT() {
    __shared__ float T[32][33];
    const int nt = blockIdx.x, dt = blockIdx.y, b = blockIdx.z;
    const float* vb = g_v + (size_t)b * Dd * Nn;
    float* vTb = g_vT + (size_t)b * Nn * Dd;
    const float* linvb = g_linv + b * Nn;
    const int tx = threadIdx.x, ty = threadIdx.y;
    for (int yy = ty; yy < 32; yy += 8)
        T[yy][tx] = vb[(size_t)(dt * 32 + yy) * Nn + nt * 32 + tx];
    __syncthreads();
    for (int yy = ty; yy < 32; yy += 8)
        vTb[(size_t)(nt * 32 + yy) * Dd + dt * 32 + tx] =
            T[tx][yy] * linvb[nt * 32 + yy];
}

// Mirror strict-upper 128-tiles of P into lower half (fully coalesced, 32x32
// smem blocks). Diagonal 128-tiles are themselves symmetric -> untouched.
__global__ void k_Ptr() {
    __shared__ float T[32][33];
    int idx = blockIdx.x >> 4;          // 0..119 strict-upper tile pair
    const int sub = blockIdx.x & 15;    // 4x4 sub-blocks of 32
    const int b = blockIdx.y;
    int i = 0;
    while (idx >= 15 - i) { idx -= 15 - i; ++i; }
    const int j = i + 1 + idx;
    const int rb = i * 128 + (sub >> 2) * 32;
    const int cb = j * 128 + (sub & 3) * 32;
    float* Pb = g_P + (size_t)b * Nn * Nn;
    const int tx = threadIdx.x, ty = threadIdx.y;
    for (int yy = ty; yy < 32; yy += 8)
        T[yy][tx] = Pb[(size_t)(rb + yy) * Nn + cb + tx];
    __syncthreads();
    for (int yy = ty; yy < 32; yy += 8)
        Pb[(size_t)(cb + yy) * Nn + rb + tx] = T[tx][yy];
}

// ---------------------------------------------------------------------------
// Kernel 1: projections. A = WT [c][d], B = x [c][n]. K = 512 (16 chunks).
// ---------------------------------------------------------------------------
__global__ __launch_bounds__(128, 2) void proj5(
    const float* __restrict__ x, const float* __restrict__ bv)
{
    extern __shared__ float sm[];
    float* bufA = sm;
    float* bufB = sm + 12288;
    const int n0 = blockIdx.x * 128, which = blockIdx.y, b = blockIdx.z;
    const int tid = threadIdx.x;
    const int tcol = (tid & 7) * 16, trow = (tid >> 3) * 8;
    const float* WT = g_wT + which * Cc * Dd;
    const float* xb = x + (size_t)b * Cc * Nn + n0;
    const u32 sA = smem_u32(bufA), sB = smem_u32(bufB);

    ull acc[8][8] = {};
    GEMM_LOOP(16, WT, Dd, xb, Nn);

    float* dst = which ? g_v : g_qk;
    #pragma unroll
    for (int r = 0; r < 8; ++r) {
        int d = trow + r;
        float add = which ? bv[d] : 0.0f;
        size_t o = ((size_t)b * Dd + d) * Nn + n0 + tcol;
        #pragma unroll
        for (int cp = 0; cp < 4; ++cp) {
            float2 e0 = upk(acc[r][2 * cp]), e1 = upk(acc[r][2 * cp + 1]);
            *(float4*)&dst[o + cp * 4] =
                make_float4(e0.x + add, e0.y + add, e1.x + add, e1.y + add);
        }
    }
}

// ---------------------------------------------------------------------------
// Kernel 2: symmetric stats, upper-triangular tile pairs (136/256). K = 128.
// Stores ONLY natural orientation (coalesced); k_Ptr mirrors afterwards.
// Row sums (and col sums for off-diagonal) atomically into g_lsum.
// ---------------------------------------------------------------------------
__global__ __launch_bounds__(128, 2) void stats6()
{
    extern __shared__ float sm[];
    float* bufA = sm;
    float* bufB = sm + 12288;
    __shared__ float lsumS[128], csumS[128];

    int idx = blockIdx.x;
    const int b = blockIdx.y;
    int i = 0;
    while (idx >= 16 - i) { idx -= 16 - i; ++i; }
    const int j = i + idx;
    const int n0 = i * 128, m0 = j * 128;
    const bool diag = (i == j);

    const int tid = threadIdx.x;
    const int tcol = (tid & 7) * 16, trow = (tid >> 3) * 8;
    const float* qkb = g_qk + (size_t)b * Dd * Nn;
    const float* An = qkb + n0;
    const float* Bm = qkb + m0;
    float* Pb = g_P + (size_t)b * Nn * Nn;
    const u32 sA = smem_u32(bufA), sB = smem_u32(bufB);

    lsumS[tid] = 0.0f; csumS[tid] = 0.0f;

    ull acc[8][8] = {};
    GEMM_LOOP(4, An, Nn, Bm, Nn);
    __syncthreads();

    float csum[16];
    #pragma unroll
    for (int c = 0; c < 16; ++c) csum[c] = 0.0f;

    #pragma unroll
    for (int r = 0; r < 8; ++r) {
        float p[16];
        float rs = 0.0f;
        #pragma unroll
        for (int cp = 0; cp < 8; ++cp) {
            float2 e2 = upk(acc[r][cp]);
            p[2 * cp]     = __expf(e2.x * INV_SCALE);
            p[2 * cp + 1] = __expf(e2.y * INV_SCALE);
        }
        #pragma unroll
        for (int c = 0; c < 16; ++c) { rs += p[c]; csum[c] += p[c]; }
        atomicAdd(&lsumS[trow + r], rs);
        size_t rb = (size_t)(n0 + trow + r) * Nn + m0 + tcol;
        *(float4*)&Pb[rb]      = make_float4(p[0],  p[1],  p[2],  p[3]);
        *(float4*)&Pb[rb + 4]  = make_float4(p[4],  p[5],  p[6],  p[7]);
        *(float4*)&Pb[rb + 8]  = make_float4(p[8],  p[9],  p[10], p[11]);
        *(float4*)&Pb[rb + 12] = make_float4(p[12], p[13], p[14], p[15]);
    }
    if (!diag) {
        #pragma unroll
        for (int c = 0; c < 16; ++c) atomicAdd(&csumS[tcol + c], csum[c]);
    }
    __syncthreads();
    atomicAdd(&g_lsum[b * Nn + n0 + tid], lsumS[tid]);
    if (!diag) atomicAdd(&g_lsum[b * Nn + m0 + tid], csumS[tid]);
}

// ---------------------------------------------------------------------------
// Kernel 3: out[d][m] = sum_n vT[n][d] * P[n][m].  128x128 tile, K = 2048
// (64 chunks).
// ---------------------------------------------------------------------------
__global__ __launch_bounds__(128, 2) void out6(float* __restrict__ out)
{
    extern __shared__ float sm[];
    float* bufA = sm;
    float* bufB = sm + 12288;
    const int m0 = blockIdx.x * 128, b = blockIdx.y;
    const int tid = threadIdx.x;
    const int tcol = (tid & 7) * 16, trow = (tid >> 3) * 8;
    const float* vTb = g_vT + (size_t)b * Nn * Dd;
    const float* Pm  = g_P  + (size_t)b * Nn * Nn + m0;
    const u32 sA = smem_u32(bufA), sB = smem_u32(bufB);

    ull acc[8][8] = {};
    GEMM_LOOP(64, vTb, Dd, Pm, Nn);

    #pragma unroll
    for (int r = 0; r < 8; ++r) {
        int d = trow + r;
        size_t o = ((size_t)b * Dd + d) * Nn + m0 + tcol;
        #pragma unroll
        for (int cp = 0; cp < 4; ++cp) {
            float2 e0 = upk(acc[r][2 * cp]), e1 = upk(acc[r][2 * cp + 1]);
            *(float4*)&out[o + cp * 4] = make_float4(e0.x, e0.y, e1.x, e1.y);
        }
    }
}

// ---------------------------------------------------------------------------
extern "C" void kernel_launch(void* const* d_in, const int* in_sizes, int n_in,
                              void* d_out, int out_size)
{
    const float* x   = (const float*)d_in[0];   // [8, 512, 2048]
    const float* wqk = (const float*)d_in[1];   // [128, 512]
    const float* wv  = (const float*)d_in[2];   // [128, 512]
    const float* bv  = (const float*)d_in[3];   // [128]
    float* out = (float*)d_out;                 // [8, 128, 2048]

    cudaFuncSetAttribute(proj5,  cudaFuncAttributeMaxDynamicSharedMemorySize, GEMM_SMEM);
    cudaFuncSetAttribute(stats6, cudaFuncAttributeMaxDynamicSharedMemorySize, GEMM_SMEM);
    cudaFuncSetAttribute(out6,   cudaFuncAttributeMaxDynamicSharedMemorySize, GEMM_SMEM);

    k_wT        <<<dim3(Cc / 32, Dd / 32, 2), dim3(32, 8)>>>(wqk, wv);
    zero_kernel <<<16, 1024>>>();
    proj5       <<<dim3(Nn / 128, 2, Bz), 128, GEMM_SMEM>>>(x, bv);
    stats6      <<<dim3(136, Bz), 128, GEMM_SMEM>>>();
    k_Ptr       <<<dim3(1920, Bz), dim3(32, 8)>>>();
    inv_kernel  <<<16, 1024>>>();
    k_vT        <<<dim3(Nn / 32, Dd / 32, Bz), dim3(32, 8)>>>();
    out6        <<<dim3(Nn / 128, Bz), 128, GEMM_SMEM>>>(out);
}

// round 17
// speedup vs baseline: 1.4632x; 1.4632x over previous
#include <cuda_runtime.h>

#define Bz 8
#define Cc 512
#define Nn 2048
#define Dd 128
#define INV_SCALE 0.08838834764831845f   // 1/sqrt(128)

typedef unsigned long long ull;
typedef unsigned int u32;

// ------------------------- scratch (__device__ globals) --------------------
__device__ float g_qk [(size_t)Bz * Dd * Nn];   // [b][d][n]  8 MB
__device__ float g_v  [(size_t)Bz * Dd * Nn];   // [b][d][n]  8 MB
__device__ float g_vT [(size_t)Bz * Nn * Dd];   // [b][n][d] = v*linv  8 MB
__device__ float g_wT [2 * Cc * Dd];            // W transposed [which][c][d]
__device__ float g_P  [(size_t)Bz * Nn * Nn];   // exp(e) unnormalized, 128 MB
__device__ float g_lsum[Bz * Nn];
__device__ float g_linv[Bz * Nn];

// ------------------------- helpers -----------------------------------------
__device__ __forceinline__ u32 smem_u32(const void* p) {
    u32 a;
    asm("{ .reg .u64 t; cvta.to.shared.u64 t, %1; cvt.u32.u64 %0, t; }"
        : "=r"(a) : "l"(p));
    return a;
}
__device__ __forceinline__ void cp16(u32 dst, const float* src) {
    asm volatile("cp.async.ca.shared.global [%0], [%1], 16;"
                 :: "r"(dst), "l"(src));
}
#define CP_COMMIT() asm volatile("cp.async.commit_group;" ::: "memory")
#define CP_WAIT(n)  asm volatile("cp.async.wait_group %0;" :: "n"(n) : "memory")

__device__ __forceinline__ void fma2(ull& d, ull a, ull b) {
    asm("fma.rn.f32x2 %0, %1, %2, %0;" : "+l"(d) : "l"(a), "l"(b));
}
__device__ __forceinline__ ull pk2(float x) {
    ull r; asm("mov.b64 %0, {%1, %1};" : "=l"(r) : "f"(x)); return r;
}
__device__ __forceinline__ float2 upk(ull v) {
    float2 f; asm("mov.b64 {%0, %1}, %2;" : "=f"(f.x), "=f"(f.y) : "l"(v)); return f;
}

// 8x8 thread tile (256 thr -> 128x128 CTA tile). Ap/Bp point at one k-row.
#define MMA8x8(Ap, Bp)                                                         \
    {                                                                          \
        float4 a0 = *(const float4*)&(Ap)[ty8];                                \
        float4 a1 = *(const float4*)&(Ap)[ty8 + 4];                            \
        ulonglong2 b01 = *(const ulonglong2*)&(Bp)[tx8];                       \
        ulonglong2 b23 = *(const ulonglong2*)&(Bp)[tx8 + 4];                   \
        float a[8] = {a0.x, a0.y, a0.z, a0.w, a1.x, a1.y, a1.z, a1.w};         \
        _Pragma("unroll")                                                      \
        for (int r = 0; r < 8; ++r) {                                          \
            ull ad = pk2(a[r]);                                                \
            fma2(acc[r][0], ad, b01.x); fma2(acc[r][1], ad, b01.y);            \
            fma2(acc[r][2], ad, b23.x); fma2(acc[r][3], ad, b23.y);            \
        }                                                                      \
    }

// stage layout: bufA stages of 4096 floats each; bufB after NSTG A-stages.
#define GISSUE(Abase, strideA, Bbase, strideB, c0, stg)                        \
    {                                                                          \
        u32 dA = sA + (stg) * 16384, dB = sB + (stg) * 16384;                  \
        _Pragma("unroll")                                                      \
        for (int q = 0; q < 4; ++q) {                                          \
            int slot = tid + q * 256;                                          \
            int row = slot >> 5, col4 = (slot & 31) * 4;                       \
            cp16(dA + slot * 16, (Abase) + (size_t)((c0) + row) * (strideA) + col4); \
            cp16(dB + slot * 16, (Bbase) + (size_t)((c0) + row) * (strideB) + col4); \
        }                                                                      \
        CP_COMMIT();                                                           \
    }

// 3-stage loop (2 CTAs/SM kernels): wait(1) -> sync -> issue(c+2) -> compute(c)
#define GEMM_LOOP3(NC, Abase, strideA, Bbase, strideB)                         \
    GISSUE(Abase, strideA, Bbase, strideB, 0, 0);                              \
    GISSUE(Abase, strideA, Bbase, strideB, 32, 1);                             \
    for (int c = 0; c < (NC); ++c) {                                           \
        if (c + 1 < (NC)) { CP_WAIT(1); } else { CP_WAIT(0); }                 \
        __syncthreads();                                                       \
        if (c + 2 < (NC))                                                      \
            GISSUE(Abase, strideA, Bbase, strideB, (c + 2) * 32, (c + 2) % 3); \
        const float* A_ = bufA + (c % 3) * 4096;                               \
        const float* B_ = bufB + (c % 3) * 4096;                               \
        _Pragma("unroll")                                                      \
        for (int kk = 0; kk < 32; ++kk) MMA8x8(A_ + kk * 128, B_ + kk * 128);  \
    }

// 6-stage loop (1 CTA/SM, 192 KB smem): deeper prefetch for DRAM-latency B.
#define GEMM_LOOP6(NC, Abase, strideA, Bbase, strideB)                         \
    GISSUE(Abase, strideA, Bbase, strideB, 0,   0);                            \
    GISSUE(Abase, strideA, Bbase, strideB, 32,  1);                            \
    GISSUE(Abase, strideA, Bbase, strideB, 64,  2);                            \
    GISSUE(Abase, strideA, Bbase, strideB, 96,  3);                            \
    GISSUE(Abase, strideA, Bbase, strideB, 128, 4);                            \
    for (int c = 0; c < (NC); ++c) {                                           \
        if (c + 4 < (NC)) { CP_WAIT(4); }                                      \
        else { CP_WAIT(0); }                                                   \
        __syncthreads();                                                       \
        if (c + 5 < (NC))                                                      \
            GISSUE(Abase, strideA, Bbase, strideB, (c + 5) * 32, (c + 5) % 6); \
        const float* A_ = bufA + (c % 6) * 4096;                               \
        const float* B_ = bufB + (c % 6) * 4096;                               \
        _Pragma("unroll")                                                      \
        for (int kk = 0; kk < 32; ++kk) MMA8x8(A_ + kk * 128, B_ + kk * 128);  \
    }

#define GEMM_SMEM3 98304
#define GEMM_SMEM6 196608

// ---------------------------------------------------------------------------
// tiny helpers
// ---------------------------------------------------------------------------
__global__ void zero_kernel() {
    int i = blockIdx.x * 1024 + threadIdx.x;
    if (i < Bz * Nn) g_lsum[i] = 0.0f;
}
__global__ void inv_kernel() {
    int i = blockIdx.x * 1024 + threadIdx.x;
    if (i < Bz * Nn) g_linv[i] = 1.0f / g_lsum[i];
}
__global__ void k_wT(const float* __restrict__ wqk, const float* __restrict__ wv) {
    __shared__ float T[32][33];
    const int ct = blockIdx.x, dt = blockIdx.y, which = blockIdx.z;
    const float* W = which ? wv : wqk;
    float* WT = g_wT + which * Cc * Dd;
    const int tx = threadIdx.x, ty = threadIdx.y;
    for (int yy = ty; yy < 32; yy += 8)
        T[yy][tx] = W[(dt * 32 + yy) * Cc + ct * 32 + tx];
    __syncthreads();
    for (int yy = ty; yy < 32; yy += 8)
        WT[(ct * 32 + yy) * Dd + dt * 32 + tx] = T[tx][yy];
}
__global__ void k_vT() {
    __shared__ float T[32][33];
    const int nt = blockIdx.x, dt = blockIdx.y, b = blockIdx.z;
    const float* vb = g_v + (size_t)b * Dd * Nn;
    float* vTb = g_vT + (size_t)b * Nn * Dd;
    const float* linvb = g_linv + b * Nn;
    const int tx = threadIdx.x, ty = threadIdx.y;
    for (int yy = ty; yy < 32; yy += 8)
        T[yy][tx] = vb[(size_t)(dt * 32 + yy) * Nn + nt * 32 + tx];
    __syncthreads();
    for (int yy = ty; yy < 32; yy += 8)
        vTb[(size_t)(nt * 32 + yy) * Dd + dt * 32 + tx] =
            T[tx][yy] * linvb[nt * 32 + yy];
}

// Mirror strict-upper 128-tiles of P into lower half (fully coalesced, 32x32
// smem blocks). Diagonal 128-tiles are themselves symmetric -> untouched.
__global__ void k_Ptr() {
    __shared__ float T[32][33];
    int idx = blockIdx.x >> 4;          // 0..119 strict-upper tile pair
    const int sub = blockIdx.x & 15;    // 4x4 sub-blocks of 32
    const int b = blockIdx.y;
    int i = 0;
    while (idx >= 15 - i) { idx -= 15 - i; ++i; }
    const int j = i + 1 + idx;
    const int rb = i * 128 + (sub >> 2) * 32;
    const int cb = j * 128 + (sub & 3) * 32;
    float* Pb = g_P + (size_t)b * Nn * Nn;
    const int tx = threadIdx.x, ty = threadIdx.y;
    for (int yy = ty; yy < 32; yy += 8)
        T[yy][tx] = Pb[(size_t)(rb + yy) * Nn + cb + tx];
    __syncthreads();
    for (int yy = ty; yy < 32; yy += 8)
        Pb[(size_t)(cb + yy) * Nn + rb + tx] = T[tx][yy];
}

// ---------------------------------------------------------------------------
// Kernel 1: projections. A = WT [c][d], B = x [c][n]. K = 512 (16 chunks).
// ---------------------------------------------------------------------------
__global__ __launch_bounds__(256, 2) void proj4(
    const float* __restrict__ x, const float* __restrict__ bv)
{
    extern __shared__ float sm[];
    float* bufA = sm;
    float* bufB = sm + 12288;
    const int n0 = blockIdx.x * 128, which = blockIdx.y, b = blockIdx.z;
    const int tid = threadIdx.x;
    const int tx8 = (tid & 15) * 8, ty8 = (tid >> 4) * 8;
    const float* WT = g_wT + which * Cc * Dd;
    const float* xb = x + (size_t)b * Cc * Nn + n0;
    const u32 sA = smem_u32(bufA), sB = smem_u32(bufB);

    ull acc[8][4] = {};
    GEMM_LOOP3(16, WT, Dd, xb, Nn);

    float* dst = which ? g_v : g_qk;
    #pragma unroll
    for (int r = 0; r < 8; ++r) {
        int d = ty8 + r;
        float add = which ? bv[d] : 0.0f;
        float2 c0 = upk(acc[r][0]), c1 = upk(acc[r][1]);
        float2 c2 = upk(acc[r][2]), c3 = upk(acc[r][3]);
        size_t o = ((size_t)b * Dd + d) * Nn + n0 + tx8;
        *(float4*)&dst[o]     = make_float4(c0.x + add, c0.y + add, c1.x + add, c1.y + add);
        *(float4*)&dst[o + 4] = make_float4(c2.x + add, c2.y + add, c3.x + add, c3.y + add);
    }
}

// ---------------------------------------------------------------------------
// Kernel 2: symmetric stats, upper-triangular tile pairs (136/256). K = 128.
// Natural-orientation store ONLY (coalesced); k_Ptr mirrors afterwards.
// Row sums (+ col sums when off-diagonal) accumulated into g_lsum.
// ---------------------------------------------------------------------------
__global__ __launch_bounds__(256, 2) void stats7()
{
    extern __shared__ float sm[];
    float* bufA = sm;
    float* bufB = sm + 12288;
    __shared__ float lsumS[128], csumS[128];

    int idx = blockIdx.x;
    const int b = blockIdx.y;
    int i = 0;
    while (idx >= 16 - i) { idx -= 16 - i; ++i; }
    const int j = i + idx;
    const int n0 = i * 128, m0 = j * 128;
    const bool diag = (i == j);

    const int tid = threadIdx.x;
    const int tx8 = (tid & 15) * 8, ty8 = (tid >> 4) * 8;
    const float* qkb = g_qk + (size_t)b * Dd * Nn;
    const float* An = qkb + n0;
    const float* Bm = qkb + m0;
    float* Pb = g_P + (size_t)b * Nn * Nn;
    const u32 sA = smem_u32(bufA), sB = smem_u32(bufB);

    if (tid < 128) { lsumS[tid] = 0.0f; csumS[tid] = 0.0f; }

    ull acc[8][4] = {};
    GEMM_LOOP3(4, An, Nn, Bm, Nn);

    // epilogue: exp, coalesced store, row + column sums
    float csum[8];
    #pragma unroll
    for (int c = 0; c < 8; ++c) csum[c] = 0.0f;

    #pragma unroll
    for (int r = 0; r < 8; ++r) {
        float p[8];
        float rs = 0.0f;
        #pragma unroll
        for (int cp = 0; cp < 4; ++cp) {
            float2 e2 = upk(acc[r][cp]);
            p[2 * cp]     = __expf(e2.x * INV_SCALE);
            p[2 * cp + 1] = __expf(e2.y * INV_SCALE);
        }
        #pragma unroll
        for (int c = 0; c < 8; ++c) { rs += p[c]; csum[c] += p[c]; }
        atomicAdd(&lsumS[ty8 + r], rs);
        size_t rb = (size_t)(n0 + ty8 + r) * Nn + m0 + tx8;
        *(float4*)&Pb[rb]     = make_float4(p[0], p[1], p[2], p[3]);
        *(float4*)&Pb[rb + 4] = make_float4(p[4], p[5], p[6], p[7]);
    }
    if (!diag) {
        #pragma unroll
        for (int c = 0; c < 8; ++c) atomicAdd(&csumS[tx8 + c], csum[c]);
    }
    __syncthreads();
    if (tid < 128) {
        atomicAdd(&g_lsum[b * Nn + n0 + tid], lsumS[tid]);
        if (!diag) atomicAdd(&g_lsum[b * Nn + m0 + tid], csumS[tid]);
    }
}

// ---------------------------------------------------------------------------
// Kernel 3: out[d][m] = sum_n vT[n][d] * P[n][m].  128x128 tile, K = 2048
// (64 chunks), 6-stage pipeline, 1 CTA/SM (grid 128).
// ---------------------------------------------------------------------------
__global__ __launch_bounds__(256, 1) void out7(float* __restrict__ out)
{
    extern __shared__ float sm[];
    float* bufA = sm;
    float* bufB = sm + 24576;   // after 6 A-stages
    const int m0 = blockIdx.x * 128, b = blockIdx.y;
    const int tid = threadIdx.x;
    const int tx8 = (tid & 15) * 8, ty8 = (tid >> 4) * 8;
    const float* vTb = g_vT + (size_t)b * Nn * Dd;
    const float* Pm  = g_P  + (size_t)b * Nn * Nn + m0;
    const u32 sA = smem_u32(bufA), sB = smem_u32(bufB);

    ull acc[8][4] = {};
    GEMM_LOOP6(64, vTb, Dd, Pm, Nn);

    #pragma unroll
    for (int r = 0; r < 8; ++r) {
        int d = ty8 + r;
        float2 c0 = upk(acc[r][0]), c1 = upk(acc[r][1]);
        float2 c2 = upk(acc[r][2]), c3 = upk(acc[r][3]);
        size_t o = ((size_t)b * Dd + d) * Nn + m0 + tx8;
        *(float4*)&out[o]     = make_float4(c0.x, c0.y, c1.x, c1.y);
        *(float4*)&out[o + 4] = make_float4(c2.x, c2.y, c3.x, c3.y);
    }
}

// ---------------------------------------------------------------------------
extern "C" void kernel_launch(void* const* d_in, const int* in_sizes, int n_in,
                              void* d_out, int out_size)
{
    const float* x   = (const float*)d_in[0];   // [8, 512, 2048]
    const float* wqk = (const float*)d_in[1];   // [128, 512]
    const float* wv  = (const float*)d_in[2];   // [128, 512]
    const float* bv  = (const float*)d_in[3];   // [128]
    float* out = (float*)d_out;                 // [8, 128, 2048]

    cudaFuncSetAttribute(proj4,  cudaFuncAttributeMaxDynamicSharedMemorySize, GEMM_SMEM3);
    cudaFuncSetAttribute(stats7, cudaFuncAttributeMaxDynamicSharedMemorySize, GEMM_SMEM3);
    cudaFuncSetAttribute(out7,   cudaFuncAttributeMaxDynamicSharedMemorySize, GEMM_SMEM6);

    k_wT        <<<dim3(Cc / 32, Dd / 32, 2), dim3(32, 8)>>>(wqk, wv);
    zero_kernel <<<16, 1024>>>();
    proj4       <<<dim3(Nn / 128, 2, Bz), 256, GEMM_SMEM3>>>(x, bv);
    stats7      <<<dim3(136, Bz), 256, GEMM_SMEM3>>>();
    k_Ptr       <<<dim3(1920, Bz), dim3(32, 8)>>>();
    inv_kernel  <<<16, 1024>>>();
    k_vT        <<<dim3(Nn / 32, Dd / 32, Bz), dim3(32, 8)>>>();
    out7        <<<dim3(Nn / 128, Bz), 256, GEMM_SMEM6>>>(out);
}